// round 5
// baseline (speedup 1.0000x reference)
#include <cuda_runtime.h>
#include <math.h>
#include <stdint.h>

#define BB 128
#define VV 128000
#define VV4 (VV / 4)
#define NBINS 8192
#define BIN_SCALE 256.0f          // bin width 1/256 over d = m - x
#define CAND_CAP 2048
#define NTH 1024
#define FINFO_MIN -3.4028234663852886e38f

#define CNT_SHIFT 47
#define MASK47 ((1ull << 47) - 1ull)
#define SCALE30 1073741824.0f     // 2^30
#define INV30 (1.0 / 1073741824.0)

// Scratch: x = logit/temp, written in pass 2, read in passes 3 & 4 (CTA-local rows).
__device__ float g_x[(size_t)BB * VV];

struct Smem {
    unsigned long long  hist[NBINS];       // packed cnt<<47 | fix30(exp); becomes inclusive prefix
    unsigned long long  cand[CAND_CAP];    // top-k candidates: key = flip(x)<<32 | ~idx
    float               pbin[CAND_CAP];    // values in the top-p cutoff bin
    double              bufA[CAND_CAP];
    double              bufB[CAND_CAP];
    unsigned long long  scan64[NTH];
    float               redf[NTH];
    // scalars
    int   cb_p, cb_k;
    unsigned int candCount, pbinCount;
    int   cntA;
    float logS;
    float xmin_kept;
    int   token;
    float xtok;
};

__device__ __forceinline__ unsigned flipf(float f) {
    unsigned u = __float_as_uint(f);
    return u ^ ((u >> 31) ? 0xFFFFFFFFu : 0x80000000u);
}
__device__ __forceinline__ float unflipf(unsigned u) {
    unsigned b = u ^ ((u & 0x80000000u) ? 0x80000000u : 0xFFFFFFFFu);
    return __uint_as_float(b);
}
__device__ __forceinline__ int binof(float d) {
    int b = (int)(d * BIN_SCALE);
    return b < 0 ? 0 : (b > NBINS - 1 ? NBINS - 1 : b);
}

// Inclusive double scan over a[0..n2), n2 = pow2 <= 2048.
// ALL NTH threads must call; barriers are unconditional.
__device__ void scan_inclusive(double* a, int n2) {
    int tid = threadIdx.x;
    for (int off = 1; off < n2; off <<= 1) {
        double v0 = 0.0, v1 = 0.0;
        int i0 = tid, i1 = tid + NTH;
        bool h0 = i0 < n2, h1 = i1 < n2;
        if (h0) { v0 = a[i0]; if (i0 >= off) v0 += a[i0 - off]; }
        if (h1) { v1 = a[i1]; if (i1 >= off) v1 += a[i1 - off]; }
        __syncthreads();
        if (h0) a[i0] = v0;
        if (h1) a[i1] = v1;
        __syncthreads();
    }
}

__global__ void __launch_bounds__(NTH, 1)
sampler_kernel(const float* __restrict__ logits,
               const float* __restrict__ temps,
               const int*   __restrict__ topks,
               const float* __restrict__ topps,
               const float* __restrict__ minps,
               const float* __restrict__ us,
               float* __restrict__ out)
{
    extern __shared__ char smem_raw[];
    Smem* sm = reinterpret_cast<Smem*>(smem_raw);
    const int row = blockIdx.x;
    const int tid = threadIdx.x;
    const int lane = tid & 31;
    const int wid  = tid >> 5;
    const float* __restrict__ rowp = logits + (size_t)row * VV;
    const float4* __restrict__ rowp4 = reinterpret_cast<const float4*>(rowp);
    float*  __restrict__ xrow  = g_x + (size_t)row * VV;
    float4* __restrict__ xrow4 = reinterpret_cast<float4*>(xrow);

    const float temp  = temps[row];
    const int   K     = topks[row];
    const float top_p = topps[row];
    const float min_p = minps[row];
    const float u     = us[row];

    // -------- init --------
    for (int i = tid; i < NBINS; i += NTH) sm->hist[i] = 0ull;
    if (tid == 0) {
        sm->candCount = 0u; sm->pbinCount = 0u; sm->cntA = 0;
        sm->cb_p = NBINS - 1; sm->cb_k = NBINS - 1;
    }

    // -------- pass 1: max over raw logits (division by positive temp is monotone,
    //          so max(logit)/temp == max(logit/temp) bit-exactly) --------
    float mt = -INFINITY;
    for (int i = tid; i < VV4; i += NTH) {
        float4 v = rowp4[i];
        mt = fmaxf(mt, fmaxf(fmaxf(v.x, v.y), fmaxf(v.z, v.w)));
    }
#pragma unroll
    for (int o = 16; o > 0; o >>= 1) mt = fmaxf(mt, __shfl_xor_sync(0xFFFFFFFFu, mt, o));
    if (lane == 0) sm->redf[wid] = mt;
    __syncthreads();
    if (tid < 32) {
        float v = sm->redf[tid];
#pragma unroll
        for (int o = 16; o > 0; o >>= 1) v = fmaxf(v, __shfl_xor_sync(0xFFFFFFFFu, v, o));
        if (tid == 0) sm->redf[0] = v;
    }
    __syncthreads();
    const float m = sm->redf[0] / temp;
    __syncthreads();

    // -------- pass 2: packed histogram over d = m - x; store x to scratch --------
    for (int i = tid; i < VV4; i += NTH) {
        float4 v = rowp4[i];
        float x0 = v.x / temp, x1 = v.y / temp, x2 = v.z / temp, x3 = v.w / temp;
        float d0 = m - x0, d1 = m - x1, d2 = m - x2, d3 = m - x3;
        float e0 = expf(-d0), e1 = expf(-d1), e2 = expf(-d2), e3 = expf(-d3);
        int b0 = binof(d0), b1 = binof(d1), b2 = binof(d2), b3 = binof(d3);
        unsigned long long p0 = (1ull << CNT_SHIFT) + (unsigned long long)(e0 * SCALE30 + 0.5f);
        unsigned long long p1 = (1ull << CNT_SHIFT) + (unsigned long long)(e1 * SCALE30 + 0.5f);
        unsigned long long p2 = (1ull << CNT_SHIFT) + (unsigned long long)(e2 * SCALE30 + 0.5f);
        unsigned long long p3 = (1ull << CNT_SHIFT) + (unsigned long long)(e3 * SCALE30 + 0.5f);
        atomicAdd(&sm->hist[b0], p0);
        atomicAdd(&sm->hist[b1], p1);
        atomicAdd(&sm->hist[b2], p2);
        atomicAdd(&sm->hist[b3], p3);
        float4 xs; xs.x = x0; xs.y = x1; xs.z = x2; xs.w = x3;
        xrow4[i] = xs;
    }
    __syncthreads();

    // -------- single packed prefix scan over bins (8 bins/thread) --------
    const int base = tid * (NBINS / NTH);
    unsigned long long lh[NBINS / NTH];
    unsigned long long hrun = 0ull;
#pragma unroll
    for (int j = 0; j < NBINS / NTH; j++) {
        hrun += sm->hist[base + j];  lh[j] = hrun;
    }
    sm->scan64[tid] = hrun;
    __syncthreads();
    for (int off = 1; off < NTH; off <<= 1) {
        unsigned long long hv = sm->scan64[tid];
        unsigned long long ha = 0ull;
        if (tid >= off) ha = sm->scan64[tid - off];
        __syncthreads();
        sm->scan64[tid] = hv + ha;
        __syncthreads();
    }
    {
        unsigned long long hex = sm->scan64[tid] - hrun;
#pragma unroll
        for (int j = 0; j < NBINS / NTH; j++)
            sm->hist[base + j] = lh[j] + hex;          // inclusive packed prefix
    }
    __syncthreads();

    const double Zh = (double)(sm->hist[NBINS - 1] & MASK47) * INV30;
    const double P  = (double)top_p * Zh;              // top-p mass threshold (exp units)

    // -------- locate cutoff bins --------
#pragma unroll
    for (int j = 0; j < NBINS / NTH; j++) {
        int g = base + j;
        unsigned long long Au = g ? sm->hist[g - 1] : 0ull;
        unsigned long long Iu = sm->hist[g];
        double A = (double)(Au & MASK47) * INV30;
        double I = (double)(Iu & MASK47) * INV30;
        if (A <= P && P < I) sm->cb_p = g;
        unsigned cA = (unsigned)(Au >> CNT_SHIFT);
        unsigned cI = (unsigned)(Iu >> CNT_SHIFT);
        if (cA < (unsigned)K && (unsigned)K <= cI) sm->cb_k = g;
    }
    __syncthreads();
    const int    cb_p  = sm->cb_p;
    const int    cb_k  = sm->cb_k;
    const double A_cbp = cb_p ? (double)(sm->hist[cb_p - 1] & MASK47) * INV30 : 0.0;

    // -------- pass 3: collect top-k candidates and top-p cutoff-bin members --------
    for (int i = tid; i < VV4; i += NTH) {
        float4 v = xrow4[i];
        float xs[4]; xs[0] = v.x; xs[1] = v.y; xs[2] = v.z; xs[3] = v.w;
#pragma unroll
        for (int j = 0; j < 4; j++) {
            float x = xs[j];
            int b = binof(m - x);
            if (b <= cb_k) {
                unsigned p = atomicAdd(&sm->candCount, 1u);
                if (p < CAND_CAP) {
                    unsigned fu = flipf(x);
                    unsigned gidx = (unsigned)(4 * i + j);
                    sm->cand[p] = ((unsigned long long)fu << 32) | (unsigned)(~gidx);
                }
            }
            if (b == cb_p) {
                unsigned q = atomicAdd(&sm->pbinCount, 1u);
                if (q < CAND_CAP) sm->pbin[q] = x;
            }
        }
    }
    __syncthreads();
    const int C   = (int)min(sm->candCount, (unsigned)CAND_CAP);
    const int npb = (int)min(sm->pbinCount, (unsigned)CAND_CAP);

    // -------- bitonic sort candidates descending (value desc, index asc) --------
    int n2 = 1; while (n2 < C) n2 <<= 1;
    for (int i = C + tid; i < n2; i += NTH) sm->cand[i] = 0ull;
    __syncthreads();
    for (int k = 2; k <= n2; k <<= 1)
        for (int j = k >> 1; j > 0; j >>= 1) {
            for (int idx = tid; idx < n2; idx += NTH) {
                int ixj = idx ^ j;
                if (ixj > idx) {
                    unsigned long long a = sm->cand[idx], b2 = sm->cand[ixj];
                    bool up = ((idx & k) == 0);
                    if (up ? (a < b2) : (a > b2)) { sm->cand[idx] = b2; sm->cand[ixj] = a; }
                }
            }
            __syncthreads();
        }

    // -------- bitonic sort cutoff-bin values descending --------
    int n2p = 1; while (n2p < npb) n2p <<= 1;
    for (int i = npb + tid; i < n2p; i += NTH) sm->pbin[i] = -INFINITY;
    __syncthreads();
    for (int k = 2; k <= n2p; k <<= 1)
        for (int j = k >> 1; j > 0; j >>= 1) {
            for (int idx = tid; idx < n2p; idx += NTH) {
                int ixj = idx ^ j;
                if (ixj > idx) {
                    float a = sm->pbin[idx], b2 = sm->pbin[ixj];
                    bool up = ((idx & k) == 0);
                    if (up ? (a < b2) : (a > b2)) { sm->pbin[idx] = b2; sm->pbin[ixj] = a; }
                }
            }
            __syncthreads();
        }

    // -------- sampling over sorted candidates --------
    {
        int i0 = tid, i1 = tid + NTH;
        bool h0 = i0 < n2, h1 = i1 < n2;
        double e0v = 0.0, e1v = 0.0;
        if (h0 && i0 < C) e0v = exp((double)(unflipf((unsigned)(sm->cand[i0] >> 32)) - m));
        if (h1 && i1 < C) e1v = exp((double)(unflipf((unsigned)(sm->cand[i1] >> 32)) - m));
        __syncthreads();
        if (h0) { sm->bufA[i0] = e0v; sm->bufB[i0] = e0v; }
        if (h1) { sm->bufA[i1] = e1v; sm->bufB[i1] = e1v; }
        __syncthreads();
    }
    scan_inclusive(sm->bufA, n2);                 // inclusive cumsum of e
    const double ehead = sm->bufB[0];
    const double thrE  = (double)min_p * ehead;   // min-p threshold (exp units)
    // ---- apply filters (flat two-slot form, uniform barriers) ----
    {
        int i0 = tid, i1 = tid + NTH;
        bool h0 = i0 < n2, h1 = i1 < n2;
        double ps0 = 0.0, ps1 = 0.0;
        if (h0 && i0 < C) {
            double e = sm->bufB[i0];
            double cumex = sm->bufA[i0] - e;
            if (i0 < K && cumex <= P && e >= thrE) ps0 = e;
        }
        if (h1 && i1 < C) {
            double e = sm->bufB[i1];
            double cumex = sm->bufA[i1] - e;
            if (i1 < K && cumex <= P && e >= thrE) ps1 = e;
        }
        __syncthreads();
        if (h0) sm->bufA[i0] = ps0;
        if (h1) sm->bufA[i1] = ps1;
        __syncthreads();
    }
    scan_inclusive(sm->bufA, n2);                 // cdf of filtered ps
    const double total  = sm->bufA[n2 - 1];
    const double target = (double)u * total;
    {
        int cnt = 0;
        for (int idx = tid; idx < C; idx += NTH)
            if (sm->bufA[idx] < target) cnt++;
        if (cnt) atomicAdd(&sm->cntA, cnt);
    }
    __syncthreads();
    if (tid == 0) {
        int s = sm->cntA; if (s > C - 1) s = C - 1;
        unsigned long long key = sm->cand[s];
        sm->token = (int)(~(unsigned)(key & 0xFFFFFFFFull));
        sm->xtok  = unflipf((unsigned)(key >> 32));
        sm->cntA  = 0;                            // reset for refinement count
    }
    __syncthreads();

    // -------- top-p cutoff-bin refinement (exact threshold + kept mass) --------
    {
        int i0 = tid, i1 = tid + NTH;
        bool h0 = i0 < n2p, h1 = i1 < n2p;
        double e0v = 0.0, e1v = 0.0;
        if (h0 && i0 < npb) e0v = exp((double)(sm->pbin[i0] - m));
        if (h1 && i1 < npb) e1v = exp((double)(sm->pbin[i1] - m));
        __syncthreads();
        if (h0) { sm->bufA[i0] = e0v; sm->bufB[i0] = e0v; }
        if (h1) { sm->bufA[i1] = e1v; sm->bufB[i1] = e1v; }
        __syncthreads();
    }
    scan_inclusive(sm->bufA, n2p);
    {
        int cnt = 0;
        for (int idx = tid; idx < npb; idx += NTH) {
            double cumex = A_cbp + (sm->bufA[idx] - sm->bufB[idx]);
            if (cumex <= P) cnt++;
        }
        if (cnt) atomicAdd(&sm->cntA, cnt);
    }
    __syncthreads();
    if (tid == 0) {
        int t = sm->cntA;
        double S = A_cbp + (t > 0 ? sm->bufA[t - 1] : 0.0);
        sm->logS = (float)log(S);
        sm->xmin_kept = (t > 0) ? sm->pbin[t - 1] : INFINITY;
    }
    __syncthreads();
    const float logS = sm->logS;
    const float xmin = sm->xmin_kept;   // kept <=> x >= xmin (bin index monotone in x; t >= 1 always)

    // -------- pass 4: write logprobs (float4, threshold-only test) --------
    float4* __restrict__ lp_out4 =
        reinterpret_cast<float4*>(out + BB + (size_t)row * VV);
    for (int i = tid; i < VV4; i += NTH) {
        float4 v = xrow4[i];
        float4 r;
        r.x = (v.x >= xmin) ? (v.x - m) - logS : FINFO_MIN;
        r.y = (v.y >= xmin) ? (v.y - m) - logS : FINFO_MIN;
        r.z = (v.z >= xmin) ? (v.z - m) - logS : FINFO_MIN;
        r.w = (v.w >= xmin) ? (v.w - m) - logS : FINFO_MIN;
        lp_out4[i] = r;
    }
    if (tid == 0) {
        out[row] = (float)sm->token;
        out[BB + (size_t)BB * VV + row] = (sm->xtok - m) - logS;
    }
}

extern "C" void kernel_launch(void* const* d_in, const int* in_sizes, int n_in,
                              void* d_out, int out_size)
{
    const float* logits = (const float*)d_in[0];
    const float* temps  = (const float*)d_in[1];
    const int*   topks  = (const int*)  d_in[2];
    const float* topps  = (const float*)d_in[3];
    const float* minps  = (const float*)d_in[4];
    const float* us     = (const float*)d_in[5];
    float* out = (float*)d_out;

    cudaFuncSetAttribute(sampler_kernel,
                         cudaFuncAttributeMaxDynamicSharedMemorySize,
                         (int)sizeof(Smem));
    sampler_kernel<<<BB, NTH, sizeof(Smem)>>>(logits, temps, topks, topps, minps, us, out);
}

// round 6
// speedup vs baseline: 1.1633x; 1.1633x over previous
#include <cuda_runtime.h>
#include <math.h>
#include <stdint.h>

#define BB 128
#define VV 128000
#define VV4 (VV / 4)
#define NBINS 8192
#define BIN_SCALE 256.0f          // bin width 1/256 over d = m - x
#define CAND_CAP 2048
#define NTH 1024
#define FINFO_MIN -3.4028234663852886e38f

#define CNT_SHIFT 47
#define MASK47 ((1ull << 47) - 1ull)
#define SCALE30 1073741824.0f     // 2^30
#define INV30 (1.0 / 1073741824.0)

struct Smem {
    unsigned long long  hist[NBINS];       // packed cnt<<47 | fix30(exp); becomes inclusive prefix
    unsigned long long  cand[CAND_CAP];    // top-k candidates: key = flip(x)<<32 | ~idx
    float               pbin[CAND_CAP];    // values in the top-p cutoff bin
    double              bufA[CAND_CAP];
    double              bufB[CAND_CAP];
    unsigned long long  scan64[NTH];
    float               redf[NTH];
    // scalars
    int   cb_p, cb_k;
    unsigned int candCount, pbinCount;
    int   cntA;
    float logS;
    float xmin_kept;
    int   token;
    float xtok;
};

__device__ __forceinline__ unsigned flipf(float f) {
    unsigned u = __float_as_uint(f);
    return u ^ ((u >> 31) ? 0xFFFFFFFFu : 0x80000000u);
}
__device__ __forceinline__ float unflipf(unsigned u) {
    unsigned b = u ^ ((u & 0x80000000u) ? 0x80000000u : 0xFFFFFFFFu);
    return __uint_as_float(b);
}
__device__ __forceinline__ int binof(float d) {
    int b = (int)(d * BIN_SCALE);
    return b < 0 ? 0 : (b > NBINS - 1 ? NBINS - 1 : b);
}

// Inclusive double scan over a[0..n2), n2 = pow2 <= 2048.
// ALL NTH threads must call; barriers are unconditional.
__device__ void scan_inclusive(double* a, int n2) {
    int tid = threadIdx.x;
    for (int off = 1; off < n2; off <<= 1) {
        double v0 = 0.0, v1 = 0.0;
        int i0 = tid, i1 = tid + NTH;
        bool h0 = i0 < n2, h1 = i1 < n2;
        if (h0) { v0 = a[i0]; if (i0 >= off) v0 += a[i0 - off]; }
        if (h1) { v1 = a[i1]; if (i1 >= off) v1 += a[i1 - off]; }
        __syncthreads();
        if (h0) a[i0] = v0;
        if (h1) a[i1] = v1;
        __syncthreads();
    }
}

__global__ void __launch_bounds__(NTH, 1)
sampler_kernel(const float* __restrict__ logits,
               const float* __restrict__ temps,
               const int*   __restrict__ topks,
               const float* __restrict__ topps,
               const float* __restrict__ minps,
               const float* __restrict__ us,
               float* __restrict__ out)
{
    extern __shared__ char smem_raw[];
    Smem* sm = reinterpret_cast<Smem*>(smem_raw);
    const int row = blockIdx.x;
    const int tid = threadIdx.x;
    const int lane = tid & 31;
    const int wid  = tid >> 5;
    const float* __restrict__ rowp = logits + (size_t)row * VV;
    const float4* __restrict__ rowp4 = reinterpret_cast<const float4*>(rowp);

    const float temp  = temps[row];
    const float invt  = 1.0f / temp;       // x = logit * invt, used identically in every pass
    const int   K     = topks[row];
    const float top_p = topps[row];
    const float min_p = minps[row];
    const float u     = us[row];

    // -------- init --------
    for (int i = tid; i < NBINS; i += NTH) sm->hist[i] = 0ull;
    if (tid == 0) {
        sm->candCount = 0u; sm->pbinCount = 0u; sm->cntA = 0;
        sm->cb_p = NBINS - 1; sm->cb_k = NBINS - 1;
    }

    // -------- pass 1: max over raw logits (mult by positive invt is monotone,
    //          so max(logit)*invt == max(logit*invt)) --------
    float mt = -INFINITY;
    for (int i = tid; i < VV4; i += NTH) {
        float4 v = rowp4[i];
        mt = fmaxf(mt, fmaxf(fmaxf(v.x, v.y), fmaxf(v.z, v.w)));
    }
#pragma unroll
    for (int o = 16; o > 0; o >>= 1) mt = fmaxf(mt, __shfl_xor_sync(0xFFFFFFFFu, mt, o));
    if (lane == 0) sm->redf[wid] = mt;
    __syncthreads();
    if (tid < 32) {
        float v = sm->redf[tid];
#pragma unroll
        for (int o = 16; o > 0; o >>= 1) v = fmaxf(v, __shfl_xor_sync(0xFFFFFFFFu, v, o));
        if (tid == 0) sm->redf[0] = v;
    }
    __syncthreads();
    const float m = sm->redf[0] * invt;
    __syncthreads();

    // -------- pass 2: packed histogram over d = m - x --------
    for (int i = tid; i < VV4; i += NTH) {
        float4 v = rowp4[i];
        float d0 = m - v.x * invt, d1 = m - v.y * invt;
        float d2 = m - v.z * invt, d3 = m - v.w * invt;
        float e0 = __expf(-d0), e1 = __expf(-d1), e2 = __expf(-d2), e3 = __expf(-d3);
        int b0 = binof(d0), b1 = binof(d1), b2 = binof(d2), b3 = binof(d3);
        unsigned long long p0 = (1ull << CNT_SHIFT) + (unsigned long long)(e0 * SCALE30 + 0.5f);
        unsigned long long p1 = (1ull << CNT_SHIFT) + (unsigned long long)(e1 * SCALE30 + 0.5f);
        unsigned long long p2 = (1ull << CNT_SHIFT) + (unsigned long long)(e2 * SCALE30 + 0.5f);
        unsigned long long p3 = (1ull << CNT_SHIFT) + (unsigned long long)(e3 * SCALE30 + 0.5f);
        atomicAdd(&sm->hist[b0], p0);
        atomicAdd(&sm->hist[b1], p1);
        atomicAdd(&sm->hist[b2], p2);
        atomicAdd(&sm->hist[b3], p3);
    }
    __syncthreads();

    // -------- single packed prefix scan over bins (8 bins/thread) --------
    const int base = tid * (NBINS / NTH);
    unsigned long long lh[NBINS / NTH];
    unsigned long long hrun = 0ull;
#pragma unroll
    for (int j = 0; j < NBINS / NTH; j++) {
        hrun += sm->hist[base + j];  lh[j] = hrun;
    }
    sm->scan64[tid] = hrun;
    __syncthreads();
    for (int off = 1; off < NTH; off <<= 1) {
        unsigned long long hv = sm->scan64[tid];
        unsigned long long ha = 0ull;
        if (tid >= off) ha = sm->scan64[tid - off];
        __syncthreads();
        sm->scan64[tid] = hv + ha;
        __syncthreads();
    }
    {
        unsigned long long hex = sm->scan64[tid] - hrun;
#pragma unroll
        for (int j = 0; j < NBINS / NTH; j++)
            sm->hist[base + j] = lh[j] + hex;          // inclusive packed prefix
    }
    __syncthreads();

    const double Zh = (double)(sm->hist[NBINS - 1] & MASK47) * INV30;
    const double P  = (double)top_p * Zh;              // top-p mass threshold (exp units)

    // -------- locate cutoff bins --------
#pragma unroll
    for (int j = 0; j < NBINS / NTH; j++) {
        int g = base + j;
        unsigned long long Au = g ? sm->hist[g - 1] : 0ull;
        unsigned long long Iu = sm->hist[g];
        double A = (double)(Au & MASK47) * INV30;
        double I = (double)(Iu & MASK47) * INV30;
        if (A <= P && P < I) sm->cb_p = g;
        unsigned cA = (unsigned)(Au >> CNT_SHIFT);
        unsigned cI = (unsigned)(Iu >> CNT_SHIFT);
        if (cA < (unsigned)K && (unsigned)K <= cI) sm->cb_k = g;
    }
    __syncthreads();
    const int    cb_p  = sm->cb_p;
    const int    cb_k  = sm->cb_k;
    const double A_cbp = cb_p ? (double)(sm->hist[cb_p - 1] & MASK47) * INV30 : 0.0;

    // -------- pass 3: collect top-k candidates and top-p cutoff-bin members --------
    for (int i = tid; i < VV4; i += NTH) {
        float4 v = rowp4[i];
        float xs[4];
        xs[0] = v.x * invt; xs[1] = v.y * invt; xs[2] = v.z * invt; xs[3] = v.w * invt;
#pragma unroll
        for (int j = 0; j < 4; j++) {
            float x = xs[j];
            int b = binof(m - x);
            if (b <= cb_k) {
                unsigned p = atomicAdd(&sm->candCount, 1u);
                if (p < CAND_CAP) {
                    unsigned fu = flipf(x);
                    unsigned gidx = (unsigned)(4 * i + j);
                    sm->cand[p] = ((unsigned long long)fu << 32) | (unsigned)(~gidx);
                }
            }
            if (b == cb_p) {
                unsigned q = atomicAdd(&sm->pbinCount, 1u);
                if (q < CAND_CAP) sm->pbin[q] = x;
            }
        }
    }
    __syncthreads();
    const int C   = (int)min(sm->candCount, (unsigned)CAND_CAP);
    const int npb = (int)min(sm->pbinCount, (unsigned)CAND_CAP);

    // -------- bitonic sort candidates descending (value desc, index asc) --------
    int n2 = 1; while (n2 < C) n2 <<= 1;
    for (int i = C + tid; i < n2; i += NTH) sm->cand[i] = 0ull;
    __syncthreads();
    for (int k = 2; k <= n2; k <<= 1)
        for (int j = k >> 1; j > 0; j >>= 1) {
            for (int idx = tid; idx < n2; idx += NTH) {
                int ixj = idx ^ j;
                if (ixj > idx) {
                    unsigned long long a = sm->cand[idx], b2 = sm->cand[ixj];
                    bool up = ((idx & k) == 0);
                    if (up ? (a < b2) : (a > b2)) { sm->cand[idx] = b2; sm->cand[ixj] = a; }
                }
            }
            __syncthreads();
        }

    // -------- bitonic sort cutoff-bin values descending --------
    int n2p = 1; while (n2p < npb) n2p <<= 1;
    for (int i = npb + tid; i < n2p; i += NTH) sm->pbin[i] = -INFINITY;
    __syncthreads();
    for (int k = 2; k <= n2p; k <<= 1)
        for (int j = k >> 1; j > 0; j >>= 1) {
            for (int idx = tid; idx < n2p; idx += NTH) {
                int ixj = idx ^ j;
                if (ixj > idx) {
                    float a = sm->pbin[idx], b2 = sm->pbin[ixj];
                    bool up = ((idx & k) == 0);
                    if (up ? (a < b2) : (a > b2)) { sm->pbin[idx] = b2; sm->pbin[ixj] = a; }
                }
            }
            __syncthreads();
        }

    // -------- sampling over sorted candidates --------
    {
        int i0 = tid, i1 = tid + NTH;
        bool h0 = i0 < n2, h1 = i1 < n2;
        double e0v = 0.0, e1v = 0.0;
        if (h0 && i0 < C) e0v = exp((double)(unflipf((unsigned)(sm->cand[i0] >> 32)) - m));
        if (h1 && i1 < C) e1v = exp((double)(unflipf((unsigned)(sm->cand[i1] >> 32)) - m));
        __syncthreads();
        if (h0) { sm->bufA[i0] = e0v; sm->bufB[i0] = e0v; }
        if (h1) { sm->bufA[i1] = e1v; sm->bufB[i1] = e1v; }
        __syncthreads();
    }
    scan_inclusive(sm->bufA, n2);                 // inclusive cumsum of e
    const double ehead = sm->bufB[0];
    const double thrE  = (double)min_p * ehead;   // min-p threshold (exp units)
    // ---- apply filters (flat two-slot form, uniform barriers) ----
    {
        int i0 = tid, i1 = tid + NTH;
        bool h0 = i0 < n2, h1 = i1 < n2;
        double ps0 = 0.0, ps1 = 0.0;
        if (h0 && i0 < C) {
            double e = sm->bufB[i0];
            double cumex = sm->bufA[i0] - e;
            if (i0 < K && cumex <= P && e >= thrE) ps0 = e;
        }
        if (h1 && i1 < C) {
            double e = sm->bufB[i1];
            double cumex = sm->bufA[i1] - e;
            if (i1 < K && cumex <= P && e >= thrE) ps1 = e;
        }
        __syncthreads();
        if (h0) sm->bufA[i0] = ps0;
        if (h1) sm->bufA[i1] = ps1;
        __syncthreads();
    }
    scan_inclusive(sm->bufA, n2);                 // cdf of filtered ps
    const double total  = sm->bufA[n2 - 1];
    const double target = (double)u * total;
    {
        int cnt = 0;
        for (int idx = tid; idx < C; idx += NTH)
            if (sm->bufA[idx] < target) cnt++;
        if (cnt) atomicAdd(&sm->cntA, cnt);
    }
    __syncthreads();
    if (tid == 0) {
        int s = sm->cntA; if (s > C - 1) s = C - 1;
        unsigned long long key = sm->cand[s];
        sm->token = (int)(~(unsigned)(key & 0xFFFFFFFFull));
        sm->xtok  = unflipf((unsigned)(key >> 32));
        sm->cntA  = 0;                            // reset for refinement count
    }
    __syncthreads();

    // -------- top-p cutoff-bin refinement (exact threshold + kept mass) --------
    {
        int i0 = tid, i1 = tid + NTH;
        bool h0 = i0 < n2p, h1 = i1 < n2p;
        double e0v = 0.0, e1v = 0.0;
        if (h0 && i0 < npb) e0v = exp((double)(sm->pbin[i0] - m));
        if (h1 && i1 < npb) e1v = exp((double)(sm->pbin[i1] - m));
        __syncthreads();
        if (h0) { sm->bufA[i0] = e0v; sm->bufB[i0] = e0v; }
        if (h1) { sm->bufA[i1] = e1v; sm->bufB[i1] = e1v; }
        __syncthreads();
    }
    scan_inclusive(sm->bufA, n2p);
    {
        int cnt = 0;
        for (int idx = tid; idx < npb; idx += NTH) {
            double cumex = A_cbp + (sm->bufA[idx] - sm->bufB[idx]);
            if (cumex <= P) cnt++;
        }
        if (cnt) atomicAdd(&sm->cntA, cnt);
    }
    __syncthreads();
    if (tid == 0) {
        int t = sm->cntA;
        double S = A_cbp + (t > 0 ? sm->bufA[t - 1] : 0.0);
        sm->logS = (float)log(S);
        sm->xmin_kept = (t > 0) ? sm->pbin[t - 1] : INFINITY;
    }
    __syncthreads();
    const float logS = sm->logS;
    const float xmin = sm->xmin_kept;   // kept <=> x >= xmin (bin index monotone in x; t >= 1 always)

    // -------- pass 4: write logprobs (float4, threshold-only test) --------
    float4* __restrict__ lp_out4 =
        reinterpret_cast<float4*>(out + BB + (size_t)row * VV);
    for (int i = tid; i < VV4; i += NTH) {
        float4 v = rowp4[i];
        float x0 = v.x * invt, x1 = v.y * invt, x2 = v.z * invt, x3 = v.w * invt;
        float4 r;
        r.x = (x0 >= xmin) ? (x0 - m) - logS : FINFO_MIN;
        r.y = (x1 >= xmin) ? (x1 - m) - logS : FINFO_MIN;
        r.z = (x2 >= xmin) ? (x2 - m) - logS : FINFO_MIN;
        r.w = (x3 >= xmin) ? (x3 - m) - logS : FINFO_MIN;
        lp_out4[i] = r;
    }
    if (tid == 0) {
        out[row] = (float)sm->token;
        out[BB + (size_t)BB * VV + row] = (sm->xtok - m) - logS;
    }
}

extern "C" void kernel_launch(void* const* d_in, const int* in_sizes, int n_in,
                              void* d_out, int out_size)
{
    const float* logits = (const float*)d_in[0];
    const float* temps  = (const float*)d_in[1];
    const int*   topks  = (const int*)  d_in[2];
    const float* topps  = (const float*)d_in[3];
    const float* minps  = (const float*)d_in[4];
    const float* us     = (const float*)d_in[5];
    float* out = (float*)d_out;

    cudaFuncSetAttribute(sampler_kernel,
                         cudaFuncAttributeMaxDynamicSharedMemorySize,
                         (int)sizeof(Smem));
    sampler_kernel<<<BB, NTH, sizeof(Smem)>>>(logits, temps, topks, topps, minps, us, out);
}